// round 1
// baseline (speedup 1.0000x reference)
#include <cuda_runtime.h>

// Problem constants (fixed by the dataset)
#define BQ 32          // batch
#define HKV 8          // kv heads
#define G 4            // gqa group size (32/8)
#define D 128          // head dim
#define PS 16          // page size
#define PAGES_PER_SEQ 256
#define CHUNKS 8
#define CHUNK_PAGES (PAGES_PER_SEQ / CHUNKS)   // 32
#define CHUNK_TOKENS (CHUNK_PAGES * PS)        // 512

// Split-KV partial scratch: [B][HKV][CHUNKS][G] (+ [D] for acc)
__device__ float g_pm[BQ * HKV * CHUNKS * G];
__device__ float g_pl[BQ * HKV * CHUNKS * G];
__device__ float g_pa[BQ * HKV * CHUNKS * G * D];

__global__ __launch_bounds__(128, 8)
void attn_partial(const float* __restrict__ q,
                  const float* __restrict__ kvc,
                  const int* __restrict__ indptr,
                  const int* __restrict__ indices,
                  const int* __restrict__ lastlen)
{
    const int chunk = blockIdx.x;
    const int h     = blockIdx.y;
    const int b     = blockIdx.z;
    const int tid   = threadIdx.x;
    const int w     = tid >> 5;
    const int lane  = tid & 31;

    __shared__ float qs[G][D];
    __shared__ int   pages[CHUNK_PAGES];
    __shared__ float sm_m[4][G];
    __shared__ float sm_l[4][G];
    __shared__ float sm_acc[4][G][D];

    const int p0     = indptr[b];
    const int npages = indptr[b + 1] - p0;
    const int valid_len = (npages - 1) * PS + lastlen[b];

    // stage q for this kv-head's 4 query heads
    for (int i = tid; i < G * D; i += 128) {
        int g = i >> 7, d = i & (D - 1);
        qs[g][d] = q[((size_t)(b * HKV * G) + h * G + g) * D + d];
    }
    // stage page indices for this chunk
    if (tid < CHUNK_PAGES) {
        int pg = chunk * CHUNK_PAGES + tid;
        pages[tid] = (pg < npages) ? indices[p0 + pg] : 0;
    }
    __syncthreads();

    const float scale = 0.08838834764831845f; // 1/sqrt(128)

    // each lane owns dims [4*lane, 4*lane+4) of q and V-acc
    float4 qv[G];
#pragma unroll
    for (int g = 0; g < G; g++)
        qv[g] = *(const float4*)&qs[g][lane * 4];

    float m[G], l[G];
    float4 acc[G];
#pragma unroll
    for (int g = 0; g < G; g++) {
        m[g] = -1e30f; l[g] = 0.f;
        acc[g] = make_float4(0.f, 0.f, 0.f, 0.f);
    }

    const int tok0 = chunk * CHUNK_TOKENS;
    int tmax = valid_len - tok0;
    if (tmax > CHUNK_TOKENS) tmax = CHUNK_TOKENS;

    const size_t v_off = (size_t)HKV * PS * D;

#pragma unroll 2
    for (int t = w; t < tmax; t += 4) {
        const int page = pages[t >> 4];
        const int pos  = t & (PS - 1);
        const size_t base = ((size_t)page * 2 * HKV + h) * (PS * D)
                          + (size_t)pos * D + lane * 4;
        const float4 k4 = *(const float4*)(kvc + base);
        const float4 v4 = *(const float4*)(kvc + base + v_off);

        float s[G];
#pragma unroll
        for (int g = 0; g < G; g++)
            s[g] = qv[g].x * k4.x + qv[g].y * k4.y + qv[g].z * k4.z + qv[g].w * k4.w;

#pragma unroll
        for (int off = 16; off; off >>= 1) {
#pragma unroll
            for (int g = 0; g < G; g++)
                s[g] += __shfl_xor_sync(0xffffffffu, s[g], off);
        }

#pragma unroll
        for (int g = 0; g < G; g++) {
            const float sv = s[g] * scale;
            const float mn = fmaxf(m[g], sv);
            const float sc = __expf(m[g] - mn);
            const float p  = __expf(sv - mn);
            l[g] = l[g] * sc + p;
            acc[g].x = acc[g].x * sc + p * v4.x;
            acc[g].y = acc[g].y * sc + p * v4.y;
            acc[g].z = acc[g].z * sc + p * v4.z;
            acc[g].w = acc[g].w * sc + p * v4.w;
            m[g] = mn;
        }
    }

    // publish per-warp partials (m,l identical across lanes after shuffles)
    if (lane == 0) {
#pragma unroll
        for (int g = 0; g < G; g++) { sm_m[w][g] = m[g]; sm_l[w][g] = l[g]; }
    }
#pragma unroll
    for (int g = 0; g < G; g++)
        *(float4*)&sm_acc[w][g][lane * 4] = acc[g];
    __syncthreads();

    // intra-CTA merge of the 4 warps; thread -> (g = tid>>5, dims 4*(tid&31))
    {
        const int g  = tid >> 5;
        const int ln = tid & 31;
        float M = sm_m[0][g];
#pragma unroll
        for (int wi = 1; wi < 4; wi++) M = fmaxf(M, sm_m[wi][g]);
        float L = 0.f;
        float4 a = make_float4(0.f, 0.f, 0.f, 0.f);
#pragma unroll
        for (int wi = 0; wi < 4; wi++) {
            const float e = __expf(sm_m[wi][g] - M);
            L += e * sm_l[wi][g];
            const float4 av = *(const float4*)&sm_acc[wi][g][ln * 4];
            a.x += e * av.x; a.y += e * av.y; a.z += e * av.z; a.w += e * av.w;
        }
        const size_t pidx = (((size_t)(b * HKV + h) * CHUNKS + chunk) * G + g);
        if (ln == 0) { g_pm[pidx] = M; g_pl[pidx] = L; }
        *(float4*)&g_pa[pidx * D + ln * 4] = a;
    }
}

__global__ __launch_bounds__(128)
void attn_combine(float* __restrict__ out)
{
    const int h = blockIdx.x;
    const int b = blockIdx.y;
    const int tid  = threadIdx.x;
    const int g    = tid >> 5;
    const int lane = tid & 31;

    const size_t base = ((size_t)(b * HKV + h) * CHUNKS) * G + g;

    float M = -1e30f;
#pragma unroll
    for (int c = 0; c < CHUNKS; c++)
        M = fmaxf(M, g_pm[base + (size_t)c * G]);

    float L = 0.f;
    float4 a = make_float4(0.f, 0.f, 0.f, 0.f);
#pragma unroll
    for (int c = 0; c < CHUNKS; c++) {
        const size_t pidx = base + (size_t)c * G;
        const float e = __expf(g_pm[pidx] - M);
        L += e * g_pl[pidx];
        const float4 av = *(const float4*)&g_pa[pidx * D + lane * 4];
        a.x += e * av.x; a.y += e * av.y; a.z += e * av.z; a.w += e * av.w;
    }
    const float inv = 1.f / L;
    float4 o = make_float4(a.x * inv, a.y * inv, a.z * inv, a.w * inv);
    // out layout: [B][H_GQA][1][D], hq = h*G + g
    *(float4*)&out[((size_t)(b * HKV * G) + h * G + g) * D + lane * 4] = o;
}

extern "C" void kernel_launch(void* const* d_in, const int* in_sizes, int n_in,
                              void* d_out, int out_size)
{
    const float* q       = (const float*)d_in[0];
    const float* kvc     = (const float*)d_in[1];
    const int*   indptr  = (const int*)d_in[2];
    const int*   indices = (const int*)d_in[3];
    const int*   lastlen = (const int*)d_in[4];
    float* out = (float*)d_out;

    dim3 g1(CHUNKS, HKV, BQ);
    attn_partial<<<g1, 128>>>(q, kvc, indptr, indices, lastlen);
    dim3 g2(HKV, BQ);
    attn_combine<<<g2, 128>>>(out);
}

// round 2
// speedup vs baseline: 1.4015x; 1.4015x over previous
#include <cuda_runtime.h>

// Problem constants (fixed by the dataset)
#define BQ 32          // batch
#define HKV 8          // kv heads
#define G 4            // gqa group size (32/8)
#define D 128          // head dim
#define PS 16          // page size
#define PAGES_PER_SEQ 256
#define CHUNKS 8
#define CHUNK_PAGES (PAGES_PER_SEQ / CHUNKS)   // 32
#define CHUNK_TOKENS (CHUNK_PAGES * PS)        // 512

// Split-KV partial scratch: [B][HKV][CHUNKS][G]
__device__ float g_pl[BQ * HKV * CHUNKS * G];
__device__ float g_pa[BQ * HKV * CHUNKS * G * D];

__device__ __forceinline__ float4 ldcs4(const float* p) {
    return __ldcs(reinterpret_cast<const float4*>(p));
}

__global__ __launch_bounds__(128, 6)
void attn_partial(const float* __restrict__ q,
                  const float* __restrict__ kvc,
                  const int* __restrict__ indptr,
                  const int* __restrict__ indices,
                  const int* __restrict__ lastlen)
{
    const int chunk = blockIdx.x;
    const int h     = blockIdx.y;
    const int b     = blockIdx.z;
    const int tid   = threadIdx.x;
    const int w     = tid >> 5;
    const int lane  = tid & 31;

    __shared__ float qs[G][D];
    __shared__ int   pages[CHUNK_PAGES];
    __shared__ float sm_l[4][G];
    __shared__ float sm_acc[4][G][D];

    const int p0     = indptr[b];
    const int npages = indptr[b + 1] - p0;
    const int valid_len = (npages - 1) * PS + lastlen[b];

    // stage q for this kv-head's 4 query heads (pre-scaled)
    const float scale = 0.08838834764831845f; // 1/sqrt(128)
    for (int i = tid; i < G * D; i += 128) {
        int g = i >> 7, d = i & (D - 1);
        qs[g][d] = q[((size_t)(b * HKV * G) + h * G + g) * D + d] * scale;
    }
    // stage page indices for this chunk
    if (tid < CHUNK_PAGES) {
        int pg = chunk * CHUNK_PAGES + tid;
        pages[tid] = (pg < npages) ? indices[p0 + pg] : 0;
    }
    __syncthreads();

    // each lane owns dims [4*lane, 4*lane+4)
    float4 qv[G];
#pragma unroll
    for (int g = 0; g < G; g++)
        qv[g] = *(const float4*)&qs[g][lane * 4];

    float l[G];
    float4 acc[G];
#pragma unroll
    for (int g = 0; g < G; g++) {
        l[g] = 0.f;
        acc[g] = make_float4(0.f, 0.f, 0.f, 0.f);
    }

    const int tok0 = chunk * CHUNK_TOKENS;
    int tmax = valid_len - tok0;
    if (tmax > CHUNK_TOKENS) tmax = CHUNK_TOKENS;

    const size_t v_off = (size_t)HKV * PS * D;
    const int lane4 = lane * 4;

    if (tmax == CHUNK_TOKENS) {
        // uniform-trip fast path: exactly 128 tokens per warp
#pragma unroll 4
        for (int i = 0; i < CHUNK_TOKENS / 4; i++) {
            const int t = w + i * 4;
            const int page = pages[t >> 4];
            const size_t base = ((size_t)page * (2 * HKV) + h) * (PS * D)
                              + (size_t)(t & (PS - 1)) * D + lane4;
            const float4 k4 = ldcs4(kvc + base);
            const float4 v4 = ldcs4(kvc + base + v_off);

            float s[G];
#pragma unroll
            for (int g = 0; g < G; g++)
                s[g] = qv[g].x * k4.x + qv[g].y * k4.y + qv[g].z * k4.z + qv[g].w * k4.w;
#pragma unroll
            for (int off = 16; off; off >>= 1) {
#pragma unroll
                for (int g = 0; g < G; g++)
                    s[g] += __shfl_xor_sync(0xffffffffu, s[g], off);
            }
#pragma unroll
            for (int g = 0; g < G; g++) {
                const float p = __expf(s[g]);
                l[g] += p;
                acc[g].x += p * v4.x;
                acc[g].y += p * v4.y;
                acc[g].z += p * v4.z;
                acc[g].w += p * v4.w;
            }
        }
    } else {
        for (int t = w; t < tmax; t += 4) {
            const int page = pages[t >> 4];
            const size_t base = ((size_t)page * (2 * HKV) + h) * (PS * D)
                              + (size_t)(t & (PS - 1)) * D + lane4;
            const float4 k4 = ldcs4(kvc + base);
            const float4 v4 = ldcs4(kvc + base + v_off);

            float s[G];
#pragma unroll
            for (int g = 0; g < G; g++)
                s[g] = qv[g].x * k4.x + qv[g].y * k4.y + qv[g].z * k4.z + qv[g].w * k4.w;
#pragma unroll
            for (int off = 16; off; off >>= 1) {
#pragma unroll
                for (int g = 0; g < G; g++)
                    s[g] += __shfl_xor_sync(0xffffffffu, s[g], off);
            }
#pragma unroll
            for (int g = 0; g < G; g++) {
                const float p = __expf(s[g]);
                l[g] += p;
                acc[g].x += p * v4.x;
                acc[g].y += p * v4.y;
                acc[g].z += p * v4.z;
                acc[g].w += p * v4.w;
            }
        }
    }

    // publish per-warp partials (l identical across lanes after butterfly)
    if (lane == 0) {
#pragma unroll
        for (int g = 0; g < G; g++) sm_l[w][g] = l[g];
    }
#pragma unroll
    for (int g = 0; g < G; g++)
        *(float4*)&sm_acc[w][g][lane4] = acc[g];
    __syncthreads();

    // intra-CTA merge of the 4 warps; thread -> (g = tid>>5, dims 4*(tid&31))
    {
        const int g  = tid >> 5;
        const int ln = tid & 31;
        float L = 0.f;
        float4 a = make_float4(0.f, 0.f, 0.f, 0.f);
#pragma unroll
        for (int wi = 0; wi < 4; wi++) {
            L += sm_l[wi][g];
            const float4 av = *(const float4*)&sm_acc[wi][g][ln * 4];
            a.x += av.x; a.y += av.y; a.z += av.z; a.w += av.w;
        }
        const size_t pidx = (((size_t)(b * HKV + h) * CHUNKS + chunk) * G + g);
        if (ln == 0) g_pl[pidx] = L;
        *(float4*)&g_pa[pidx * D + ln * 4] = a;
    }
}

__global__ __launch_bounds__(128)
void attn_combine(float* __restrict__ out)
{
    const int h = blockIdx.x;
    const int b = blockIdx.y;
    const int tid  = threadIdx.x;
    const int g    = tid >> 5;
    const int lane = tid & 31;

    const size_t base = ((size_t)(b * HKV + h) * CHUNKS) * G + g;

    float L = 0.f;
    float4 a = make_float4(0.f, 0.f, 0.f, 0.f);
#pragma unroll
    for (int c = 0; c < CHUNKS; c++) {
        const size_t pidx = base + (size_t)c * G;
        L += g_pl[pidx];
        const float4 av = *(const float4*)&g_pa[pidx * D + lane * 4];
        a.x += av.x; a.y += av.y; a.z += av.z; a.w += av.w;
    }
    const float inv = 1.f / L;
    float4 o = make_float4(a.x * inv, a.y * inv, a.z * inv, a.w * inv);
    // out layout: [B][H_GQA][1][D], hq = h*G + g
    *(float4*)&out[((size_t)(b * HKV * G) + h * G + g) * D + lane * 4] = o;
}

extern "C" void kernel_launch(void* const* d_in, const int* in_sizes, int n_in,
                              void* d_out, int out_size)
{
    const float* q       = (const float*)d_in[0];
    const float* kvc     = (const float*)d_in[1];
    const int*   indptr  = (const int*)d_in[2];
    const int*   indices = (const int*)d_in[3];
    const int*   lastlen = (const int*)d_in[4];
    float* out = (float*)d_out;

    dim3 g1(CHUNKS, HKV, BQ);
    attn_partial<<<g1, 128>>>(q, kvc, indptr, indices, lastlen);
    dim3 g2(HKV, BQ);
    attn_combine<<<g2, 128>>>(out);
}

// round 3
// speedup vs baseline: 1.8147x; 1.2948x over previous
#include <cuda_runtime.h>

// Problem constants (fixed by the dataset)
#define BQ 32          // batch
#define HKV 8          // kv heads
#define G 4            // gqa group size (32/8)
#define D 128          // head dim
#define PS 16          // page size
#define PAGES_PER_SEQ 256
#define CHUNKS 8
#define CHUNK_PAGES (PAGES_PER_SEQ / CHUNKS)   // 32
#define CHUNK_TOKENS (CHUNK_PAGES * PS)        // 512

// Split-KV partial scratch: [B][HKV][CHUNKS][G]
__device__ float g_pl[BQ * HKV * CHUNKS * G];
__device__ float g_pa[BQ * HKV * CHUNKS * G * D];

__device__ __forceinline__ float4 ldcs4(const float* p) {
    return __ldcs(reinterpret_cast<const float4*>(p));
}

union f2u { float2 f; unsigned long long u; };

// packed 2xfp32 fma (Blackwell f32x2 pipe) — halves FMA-pipe issue count
__device__ __forceinline__ float2 ffma2(float2 a, float2 b, float2 c) {
    f2u A, B, C, Dd; A.f = a; B.f = b; C.f = c;
    asm("fma.rn.f32x2 %0, %1, %2, %3;" : "=l"(Dd.u) : "l"(A.u), "l"(B.u), "l"(C.u));
    return Dd.f;
}
__device__ __forceinline__ float2 fadd2(float2 a, float2 b) {
    f2u A, B, Dd; A.f = a; B.f = b;
    asm("add.rn.f32x2 %0, %1, %2;" : "=l"(Dd.u) : "l"(A.u), "l"(B.u));
    return Dd.f;
}

struct AttState {
    float2 q_lo[G], q_hi[G];      // prescaled q, this lane's 4 dims
    float2 acc_lo[G], acc_hi[G];  // V accumulators
    float2 l01, l23;              // sum of weights, heads 0/1 and 2/3
};

// process one token given its K/V float4 for this lane's dims
__device__ __forceinline__ void proc_token(AttState& st, float4 k4, float4 v4) {
    const float2 klo = make_float2(k4.x, k4.y), khi = make_float2(k4.z, k4.w);
    const float2 vlo = make_float2(v4.x, v4.y), vhi = make_float2(v4.z, v4.w);
    float s[G];
#pragma unroll
    for (int g = 0; g < G; g++) {
        float2 d2 = ffma2(st.q_lo[g], klo, make_float2(0.f, 0.f));
        d2 = ffma2(st.q_hi[g], khi, d2);
        s[g] = d2.x + d2.y;
    }
#pragma unroll
    for (int off = 16; off; off >>= 1) {
#pragma unroll
        for (int g = 0; g < G; g++)
            s[g] += __shfl_xor_sync(0xffffffffu, s[g], off);
    }
    float p[G];
#pragma unroll
    for (int g = 0; g < G; g++) p[g] = exp2f(s[g]);   // q prescaled by scale*log2e
    st.l01 = fadd2(st.l01, make_float2(p[0], p[1]));
    st.l23 = fadd2(st.l23, make_float2(p[2], p[3]));
#pragma unroll
    for (int g = 0; g < G; g++) {
        const float2 p2 = make_float2(p[g], p[g]);
        st.acc_lo[g] = ffma2(p2, vlo, st.acc_lo[g]);
        st.acc_hi[g] = ffma2(p2, vhi, st.acc_hi[g]);
    }
}

__global__ __launch_bounds__(128, 5)
void attn_partial(const float* __restrict__ q,
                  const float* __restrict__ kvc,
                  const int* __restrict__ indptr,
                  const int* __restrict__ indices,
                  const int* __restrict__ lastlen)
{
    const int chunk = blockIdx.x;
    const int h     = blockIdx.y;
    const int b     = blockIdx.z;
    const int tid   = threadIdx.x;
    const int w     = tid >> 5;
    const int lane  = tid & 31;

    __shared__ float qs[G][D];
    __shared__ int   pages[CHUNK_PAGES];
    __shared__ float sm_l[4][G];
    __shared__ float sm_acc[4][G][D];

    const int p0     = indptr[b];
    const int npages = indptr[b + 1] - p0;
    const int valid_len = (npages - 1) * PS + lastlen[b];

    // stage q (pre-scaled by 1/sqrt(D) * log2(e) so softmax uses exp2)
    const float scale = 0.08838834764831845f * 1.4426950408889634f;
    for (int i = tid; i < G * D; i += 128) {
        int g = i >> 7, d = i & (D - 1);
        qs[g][d] = q[((size_t)(b * HKV * G) + h * G + g) * D + d] * scale;
    }
    if (tid < CHUNK_PAGES) {
        int pg = chunk * CHUNK_PAGES + tid;
        pages[tid] = (pg < npages) ? indices[p0 + pg] : 0;
    }
    __syncthreads();

    const int lane4 = lane * 4;

    AttState st;
#pragma unroll
    for (int g = 0; g < G; g++) {
        const float4 qv = *(const float4*)&qs[g][lane4];
        st.q_lo[g] = make_float2(qv.x, qv.y);
        st.q_hi[g] = make_float2(qv.z, qv.w);
        st.acc_lo[g] = make_float2(0.f, 0.f);
        st.acc_hi[g] = make_float2(0.f, 0.f);
    }
    st.l01 = make_float2(0.f, 0.f);
    st.l23 = make_float2(0.f, 0.f);

    const int tok0 = chunk * CHUNK_TOKENS;
    int tmax = valid_len - tok0;
    if (tmax > CHUNK_TOKENS) tmax = CHUNK_TOKENS;

    const size_t v_off = (size_t)HKV * PS * D;   // in floats
    const int full_pages = tmax >> 4;            // complete pages in this chunk

    // fast path: full pages; warp w owns positions {w, w+4, w+8, w+12}
    for (int pg = 0; pg < full_pages; pg++) {
        const float* base = kvc
            + ((size_t)pages[pg] * (2 * HKV) + h) * (PS * D)
            + (size_t)w * D + lane4;
        // 8 loads, immediate offsets (pos stride 4 tokens = 512 floats)
        const float4 k0 = ldcs4(base);
        const float4 k1 = ldcs4(base + 512);
        const float4 k2 = ldcs4(base + 1024);
        const float4 k3 = ldcs4(base + 1536);
        const float4 v0 = ldcs4(base + v_off);
        const float4 v1 = ldcs4(base + v_off + 512);
        const float4 v2 = ldcs4(base + v_off + 1024);
        const float4 v3 = ldcs4(base + v_off + 1536);
        proc_token(st, k0, v0);
        proc_token(st, k1, v1);
        proc_token(st, k2, v2);
        proc_token(st, k3, v3);
    }

    // tail: partial last page (only the final chunk of a sequence hits this)
    for (int t = full_pages * PS + w; t < tmax; t += 4) {
        const float* base = kvc
            + ((size_t)pages[t >> 4] * (2 * HKV) + h) * (PS * D)
            + (size_t)(t & (PS - 1)) * D + lane4;
        proc_token(st, ldcs4(base), ldcs4(base + v_off));
    }

    // publish per-warp partials (l replicated across lanes after butterfly)
    if (lane == 0) {
        sm_l[w][0] = st.l01.x; sm_l[w][1] = st.l01.y;
        sm_l[w][2] = st.l23.x; sm_l[w][3] = st.l23.y;
    }
#pragma unroll
    for (int g = 0; g < G; g++) {
        float4 a = make_float4(st.acc_lo[g].x, st.acc_lo[g].y,
                               st.acc_hi[g].x, st.acc_hi[g].y);
        *(float4*)&sm_acc[w][g][lane4] = a;
    }
    __syncthreads();

    // intra-CTA merge; thread -> (g = tid>>5, dims 4*(tid&31))
    {
        const int g  = tid >> 5;
        const int ln = tid & 31;
        float L = 0.f;
        float4 a = make_float4(0.f, 0.f, 0.f, 0.f);
#pragma unroll
        for (int wi = 0; wi < 4; wi++) {
            L += sm_l[wi][g];
            const float4 av = *(const float4*)&sm_acc[wi][g][ln * 4];
            a.x += av.x; a.y += av.y; a.z += av.z; a.w += av.w;
        }
        const size_t pidx = (((size_t)(b * HKV + h) * CHUNKS + chunk) * G + g);
        if (ln == 0) g_pl[pidx] = L;
        *(float4*)&g_pa[pidx * D + ln * 4] = a;
    }
}

__global__ __launch_bounds__(128)
void attn_combine(float* __restrict__ out)
{
    const int h = blockIdx.x;
    const int b = blockIdx.y;
    const int tid  = threadIdx.x;
    const int g    = tid >> 5;
    const int lane = tid & 31;

    const size_t base = ((size_t)(b * HKV + h) * CHUNKS) * G + g;

    float L = 0.f;
    float4 a = make_float4(0.f, 0.f, 0.f, 0.f);
#pragma unroll
    for (int c = 0; c < CHUNKS; c++) {
        const size_t pidx = base + (size_t)c * G;
        L += g_pl[pidx];
        const float4 av = *(const float4*)&g_pa[pidx * D + lane * 4];
        a.x += av.x; a.y += av.y; a.z += av.z; a.w += av.w;
    }
    const float inv = 1.f / L;
    float4 o = make_float4(a.x * inv, a.y * inv, a.z * inv, a.w * inv);
    *(float4*)&out[((size_t)(b * HKV * G) + h * G + g) * D + lane * 4] = o;
}

extern "C" void kernel_launch(void* const* d_in, const int* in_sizes, int n_in,
                              void* d_out, int out_size)
{
    const float* q       = (const float*)d_in[0];
    const float* kvc     = (const float*)d_in[1];
    const int*   indptr  = (const int*)d_in[2];
    const int*   indices = (const int*)d_in[3];
    const int*   lastlen = (const int*)d_in[4];
    float* out = (float*)d_out;

    dim3 g1(CHUNKS, HKV, BQ);
    attn_partial<<<g1, 128>>>(q, kvc, indptr, indices, lastlen);
    dim3 g2(HKV, BQ);
    attn_combine<<<g2, 128>>>(out);
}